// round 17
// baseline (speedup 1.0000x reference)
#include <cuda_runtime.h>
#include <cuda_bf16.h>
#include <mma.h>
#include <cstdint>

using namespace nvcuda;

#define NN     50000
#define NN_PAD 50048                 // 391 * 128
#define DIM    128
#define KT     512                   // NB * DIM
#define NB     4
#define NR     100
#define NE     800000
#define MTILES 782                   // NN_PAD / 64

// ---------------------------------------------------------------------------
// Device scratch (zero-initialized at load; padded/untouched rows stay zero).
// ---------------------------------------------------------------------------
__device__ __nv_bfloat16 g_h1[(size_t)NN_PAD * DIM];     // bf16 limbs of h
__device__ __nv_bfloat16 g_h2[(size_t)NN_PAD * DIM];
__device__ __nv_bfloat16 g_t1[(size_t)NN_PAD * KT];      // bf16 limbs of norm*t
__device__ __nv_bfloat16 g_t2[(size_t)NN_PAD * KT];
__device__ __nv_bfloat16 g_wt[(size_t)5 * 2 * DIM * DIM]; // W^T limbs [mat][limb][n][k]
// CSR-by-dst scratch
__device__ int g_cnt[NN];
__device__ int g_rowptr[NN + 1];
__device__ int g_epack[NE];          // src | rel << 17

// ---------------------------------------------------------------------------
// bf16x2 split of h (K-chunk 4 of the fused GEMM)
// ---------------------------------------------------------------------------
__global__ void split_h_kernel(const float* __restrict__ h) {
    int i = blockIdx.x * blockDim.x + threadIdx.x;
    if (i >= NN * DIM) return;
    float x = h[i];
    __nv_bfloat16 b1 = __float2bfloat16(x);
    float r1 = x - __bfloat162float(b1);
    g_h1[i] = b1;
    g_h2[i] = __float2bfloat16(r1);
}

// bf16x2 split of W, transposed to [n][k]; mats 0..3 = bases, 4 = loop
__global__ void split_w_kernel(const float* __restrict__ basis,
                               const float* __restrict__ loopw) {
    int i = blockIdx.x * blockDim.x + threadIdx.x;
    if (i >= 5 * DIM * DIM) return;
    int mat = i / (DIM * DIM);
    int rem = i - mat * DIM * DIM;
    int n = rem / DIM, k = rem - (rem / DIM) * DIM;
    float x = (mat < NB) ? basis[(size_t)mat * DIM * DIM + k * DIM + n]
                         : loopw[k * DIM + n];
    __nv_bfloat16 b1 = __float2bfloat16(x);
    float r1 = x - __bfloat162float(b1);
    size_t base = (size_t)mat * 2 * DIM * DIM + (size_t)n * DIM + k;
    g_wt[base]             = b1;
    g_wt[base + DIM * DIM] = __float2bfloat16(r1);
}

// ---------------------------------------------------------------------------
// CSR build (by DST): zero counters -> histogram -> 1-CTA scan -> scatter.
// ---------------------------------------------------------------------------
__global__ void zero_cnt_kernel() {
    int i = blockIdx.x * blockDim.x + threadIdx.x;
    if (i < NN) g_cnt[i] = 0;
}

__global__ void hist_kernel(const int* __restrict__ dst) {
    int e = blockIdx.x * blockDim.x + threadIdx.x;
    if (e < NE) atomicAdd(&g_cnt[dst[e]], 1);
}

__global__ void scan_kernel() {      // 1 CTA, 1024 threads
    __shared__ int psum[1024];
    const int t = threadIdx.x;
    const int CH = (NN + 1023) / 1024;   // 49
    int beg = t * CH;
    int end = beg + CH; if (end > NN) end = NN;
    int s = 0;
    for (int i = beg; i < end; i++) s += g_cnt[i];
    psum[t] = s;
    __syncthreads();
    for (int off = 1; off < 1024; off <<= 1) {
        int v = (t >= off) ? psum[t - off] : 0;
        __syncthreads();
        psum[t] += v;
        __syncthreads();
    }
    int base = (t > 0) ? psum[t - 1] : 0;
    for (int i = beg; i < end; i++) {
        int c = g_cnt[i];
        g_rowptr[i] = base;
        g_cnt[i]    = base;          // becomes scatter cursor
        base += c;
    }
    if (t == 1023) g_rowptr[NN] = psum[1023];
}

__global__ void scatter_kernel(const int* __restrict__ src,
                               const int* __restrict__ dst,
                               const int* __restrict__ rel) {
    int e = blockIdx.x * blockDim.x + threadIdx.x;
    if (e >= NE) return;
    int pos = atomicAdd(&g_cnt[dst[e]], 1);
    g_epack[pos] = src[e] | (rel[e] << 17);
}

// ---------------------------------------------------------------------------
// Edge kernel: one warp per DST node. Accumulate t[n][b][:] in registers,
// scale by norm[n] (linearity: agg*norm == (norm*t)@basis), emit bf16 limbs.
// ---------------------------------------------------------------------------
__global__ __launch_bounds__(256) void edge_t_kernel(const float* __restrict__ h,
                                                     const float* __restrict__ coeff,
                                                     const float* __restrict__ norm) {
    int n    = (blockIdx.x * blockDim.x + threadIdx.x) >> 5;
    int lane = threadIdx.x & 31;
    if (n >= NN) return;

    const int beg = __ldg(&g_rowptr[n]);
    const int end = __ldg(&g_rowptr[n + 1]);

    float4 acc[NB];
    #pragma unroll
    for (int b = 0; b < NB; b++) acc[b] = make_float4(0.f, 0.f, 0.f, 0.f);

    const float4* h4 = (const float4*)h;

    int e = beg;
    for (; e + 1 < end; e += 2) {
        int p0 = __ldg(&g_epack[e]);
        int p1 = __ldg(&g_epack[e + 1]);
        float4 v0 = h4[(size_t)(p0 & 131071) * 32 + lane];
        float4 v1 = h4[(size_t)(p1 & 131071) * 32 + lane];
        float4 c0 = *(const float4*)(coeff + (p0 >> 17) * 4);
        float4 c1 = *(const float4*)(coeff + (p1 >> 17) * 4);
        #pragma unroll
        for (int b = 0; b < NB; b++) {
            float cb0 = (&c0.x)[b];
            acc[b].x = fmaf(cb0, v0.x, acc[b].x);
            acc[b].y = fmaf(cb0, v0.y, acc[b].y);
            acc[b].z = fmaf(cb0, v0.z, acc[b].z);
            acc[b].w = fmaf(cb0, v0.w, acc[b].w);
            float cb1 = (&c1.x)[b];
            acc[b].x = fmaf(cb1, v1.x, acc[b].x);
            acc[b].y = fmaf(cb1, v1.y, acc[b].y);
            acc[b].z = fmaf(cb1, v1.z, acc[b].z);
            acc[b].w = fmaf(cb1, v1.w, acc[b].w);
        }
    }
    if (e < end) {
        int p0 = __ldg(&g_epack[e]);
        float4 v0 = h4[(size_t)(p0 & 131071) * 32 + lane];
        float4 c0 = *(const float4*)(coeff + (p0 >> 17) * 4);
        #pragma unroll
        for (int b = 0; b < NB; b++) {
            float cb0 = (&c0.x)[b];
            acc[b].x = fmaf(cb0, v0.x, acc[b].x);
            acc[b].y = fmaf(cb0, v0.y, acc[b].y);
            acc[b].z = fmaf(cb0, v0.z, acc[b].z);
            acc[b].w = fmaf(cb0, v0.w, acc[b].w);
        }
    }

    const float nm = __ldg(&norm[n]);

    #pragma unroll
    for (int b = 0; b < NB; b++) {
        size_t o = (size_t)n * KT + b * DIM + lane * 4;
        float4 a = acc[b];
        a.x *= nm; a.y *= nm; a.z *= nm; a.w *= nm;
        __nv_bfloat16 x1 = __float2bfloat16(a.x);
        __nv_bfloat16 y1 = __float2bfloat16(a.y);
        __nv_bfloat16 z1 = __float2bfloat16(a.z);
        __nv_bfloat16 w1 = __float2bfloat16(a.w);
        ((__nv_bfloat162*)(g_t1 + o))[0] = __halves2bfloat162(x1, y1);
        ((__nv_bfloat162*)(g_t1 + o))[1] = __halves2bfloat162(z1, w1);
        ((__nv_bfloat162*)(g_t2 + o))[0] = __halves2bfloat162(
            __float2bfloat16(a.x - __bfloat162float(x1)),
            __float2bfloat16(a.y - __bfloat162float(y1)));
        ((__nv_bfloat162*)(g_t2 + o))[1] = __halves2bfloat162(
            __float2bfloat16(a.z - __bfloat162float(z1)),
            __float2bfloat16(a.w - __bfloat162float(w1)));
    }
}

// ---------------------------------------------------------------------------
// Fused wmma GEMM, K = 640 in 5 chunks:
//   chunks 0-3: A = norm*t limbs, B = basis[c]^T limbs
//   chunk  4  : A = h limbs,      B = loopW^T limbs
// relu applied to accumulator fragments; stored straight to d_out.
// 50000 % 16 == 0 -> per-fragment row guard is exact.
// ---------------------------------------------------------------------------
#define SM_STRIDE 136
#define SM_A_LIMB (64 * SM_STRIDE)
#define SM_B_LIMB (128 * SM_STRIDE)
#define SM_TOTAL  ((2 * SM_A_LIMB + 2 * SM_B_LIMB) * 2)   // 104448 bytes

__global__ void __launch_bounds__(128, 2) gemm_fused_kernel(float* __restrict__ out) {
    extern __shared__ __nv_bfloat16 smem[];
    __nv_bfloat16* As = smem;
    __nv_bfloat16* Bs = smem + 2 * SM_A_LIMB;

    const int tid = threadIdx.x;
    const int wid = tid >> 5;
    const int m0  = blockIdx.x * 64;

    const int wm = (wid >> 1) * 32;
    const int wn = (wid & 1) * 64;

    wmma::fragment<wmma::accumulator, 16, 16, 16, float> acc[2][4];
    #pragma unroll
    for (int i = 0; i < 2; i++)
        #pragma unroll
        for (int j = 0; j < 4; j++) wmma::fill_fragment(acc[i][j], 0.0f);

    #pragma unroll
    for (int kc = 0; kc < 5; kc++) {
        const bool tchunk = (kc < NB);
        const int strideA = tchunk ? KT : DIM;
        const __nv_bfloat16* a1 = tchunk ? g_t1 + (size_t)m0 * KT + kc * DIM
                                         : g_h1 + (size_t)m0 * DIM;
        const __nv_bfloat16* a2 = tchunk ? g_t2 + (size_t)m0 * KT + kc * DIM
                                         : g_h2 + (size_t)m0 * DIM;
        // ---- Stage A limbs (64 x 128) and B limbs (128 x 128).
        #pragma unroll
        for (int it = 0; it < 8; it++) {
            int idx = it * 128 + tid;          // 0..1023 16B chunks
            int row = idx >> 4;
            int c8  = (idx & 15) * 8;
            *(float4*)(As + row * SM_STRIDE + c8) =
                *(const float4*)(a1 + (size_t)row * strideA + c8);
            *(float4*)(As + SM_A_LIMB + row * SM_STRIDE + c8) =
                *(const float4*)(a2 + (size_t)row * strideA + c8);
        }
        const __nv_bfloat16* wb = g_wt + (size_t)kc * 2 * DIM * DIM;
        #pragma unroll
        for (int it = 0; it < 16; it++) {
            int idx = it * 128 + tid;          // 0..2047
            int row = idx >> 4;
            int c8  = (idx & 15) * 8;
            *(float4*)(Bs + row * SM_STRIDE + c8) =
                *(const float4*)(wb + (size_t)row * DIM + c8);
            *(float4*)(Bs + SM_B_LIMB + row * SM_STRIDE + c8) =
                *(const float4*)(wb + DIM * DIM + (size_t)row * DIM + c8);
        }
        __syncthreads();

        #pragma unroll 4
        for (int k = 0; k < DIM; k += 16) {
            wmma::fragment<wmma::matrix_a, 16, 16, 16, __nv_bfloat16, wmma::row_major> af[2][2];
            #pragma unroll
            for (int s = 0; s < 2; s++) {
                wmma::load_matrix_sync(af[s][0], As + s * SM_A_LIMB + (wm     ) * SM_STRIDE + k, SM_STRIDE);
                wmma::load_matrix_sync(af[s][1], As + s * SM_A_LIMB + (wm + 16) * SM_STRIDE + k, SM_STRIDE);
            }
            wmma::fragment<wmma::matrix_b, 16, 16, 16, __nv_bfloat16, wmma::col_major> bf[2][4];
            #pragma unroll
            for (int s = 0; s < 2; s++)
                #pragma unroll
                for (int j = 0; j < 4; j++)
                    wmma::load_matrix_sync(bf[s][j],
                        Bs + s * SM_B_LIMB + (wn + j * 16) * SM_STRIDE + k, SM_STRIDE);
            #pragma unroll
            for (int i = 0; i < 2; i++)
                #pragma unroll
                for (int j = 0; j < 4; j++) {
                    wmma::mma_sync(acc[i][j], af[0][i], bf[0][j], acc[i][j]);
                    wmma::mma_sync(acc[i][j], af[0][i], bf[1][j], acc[i][j]);
                    wmma::mma_sync(acc[i][j], af[1][i], bf[0][j], acc[i][j]);
                }
        }
        __syncthreads();
    }

    // ---- Epilogue: relu on fragments, guarded store straight to d_out.
    #pragma unroll
    for (int i = 0; i < 2; i++)
        #pragma unroll
        for (int j = 0; j < 4; j++) {
            int mrow = m0 + wm + i * 16;
            if (mrow < NN) {                       // 16-row frag fully valid (NN % 16 == 0)
                #pragma unroll
                for (int t = 0; t < acc[i][j].num_elements; t++)
                    acc[i][j].x[t] = fmaxf(acc[i][j].x[t], 0.0f);
                wmma::store_matrix_sync(out + (size_t)mrow * DIM + wn + j * 16,
                                        acc[i][j], DIM, wmma::mem_row_major);
            }
        }
}

// ---------------------------------------------------------------------------
extern "C" void kernel_launch(void* const* d_in, const int* in_sizes, int n_in,
                              void* d_out, int out_size) {
    const float* h     = (const float*)d_in[0];
    const float* norm  = (const float*)d_in[1];
    const int*   src   = (const int*)  d_in[2];
    const int*   dst   = (const int*)  d_in[3];
    const int*   rel   = (const int*)  d_in[4];
    const float* basis = (const float*)d_in[5];
    const float* coeff = (const float*)d_in[6];
    const float* loopw = (const float*)d_in[7];
    float* out = (float*)d_out;

    static bool attr_done = false;
    if (!attr_done) {
        cudaFuncSetAttribute(gemm_fused_kernel,
                             cudaFuncAttributeMaxDynamicSharedMemorySize, SM_TOTAL);
        attr_done = true;
    }

    // CSR by dst
    zero_cnt_kernel<<<(NN + 255) / 256, 256>>>();
    hist_kernel<<<(NE + 255) / 256, 256>>>(dst);
    scan_kernel<<<1, 1024>>>();
    scatter_kernel<<<(NE + 255) / 256, 256>>>(src, dst, rel);

    split_h_kernel<<<(NN * DIM + 255) / 256, 256>>>(h);
    split_w_kernel<<<(5 * DIM * DIM + 255) / 256, 256>>>(basis, loopw);

    // Input-space aggregation by dst (no atomics), pre-scaled by norm.
    edge_t_kernel<<<(NN * 32 + 255) / 256, 256>>>(h, coeff, norm);

    // Single fused GEMM (K=640) with relu epilogue -> d_out.
    gemm_fused_kernel<<<MTILES, 128, SM_TOTAL>>>(out);
}